// round 1
// baseline (speedup 1.0000x reference)
#include <cuda_runtime.h>
#include <cuda_bf16.h>

// Problem constants (Swin window attention)
#define WIN    7
#define NTOK   49          // tokens per window
#define DIM    512
#define HEADS  16
#define HD     32          // head dim
#define BW     2048        // batch * windows
#define M_TOT  (BW * NTOK) // 100352 total tokens
#define THREEC 1536

// Scratch (allocation-free: __device__ globals)
__device__ float g_q[BW * HEADS * NTOK * HD];   // (b, h, n, d), pre-scaled
__device__ float g_k[BW * HEADS * NTOK * HD];   // (b, h, n, d)
__device__ float g_v[BW * HEADS * NTOK * HD];   // (b, h, n, d)
__device__ float g_att[M_TOT * DIM];            // (b*n, h*HD+d) attention output

// ---------------------------------------------------------------------------
// Kernel 1: QKV GEMM.  C[100352, 1536] = x[100352,512] @ w_qkv[512,1536] + b
// Epilogue scatters into g_q (scaled by d^-0.5), g_k, g_v in (b,h,n,d) layout.
// Tiling: 128x128 block tile, BK=8, 8x8 per thread, 256 threads.
// Grid: (1536/128, 100352/128) = (12, 784). M divides exactly -> no bounds.
// ---------------------------------------------------------------------------
__global__ __launch_bounds__(256) void qkv_gemm(const float* __restrict__ A,
                                                const float* __restrict__ B,
                                                const float* __restrict__ bias) {
    __shared__ float As[8][128];
    __shared__ float Bs[8][128];

    const int tid  = threadIdx.x;
    const int cRow = blockIdx.y;
    const int cCol = blockIdx.x;

    const int tCol = tid & 15;   // 16 thread-cols
    const int tRow = tid >> 4;   // 16 thread-rows

    const int aRow = tid >> 1;          // 0..127
    const int aCol = (tid & 1) << 2;    // 0 or 4
    const int bRow = tid >> 5;          // 0..7
    const int bCol = (tid & 31) << 2;   // 0..124

    const float* Ab = A + (size_t)cRow * 128 * DIM;
    const float* Bb = B + cCol * 128;

    float acc[8][8];
#pragma unroll
    for (int i = 0; i < 8; i++)
#pragma unroll
        for (int j = 0; j < 8; j++) acc[i][j] = 0.f;

    for (int k0 = 0; k0 < DIM; k0 += 8) {
        float4 a4 = *(const float4*)(Ab + aRow * DIM + k0 + aCol);
        As[aCol + 0][aRow] = a4.x;
        As[aCol + 1][aRow] = a4.y;
        As[aCol + 2][aRow] = a4.z;
        As[aCol + 3][aRow] = a4.w;
        *(float4*)(&Bs[bRow][bCol]) =
            *(const float4*)(Bb + (size_t)(k0 + bRow) * THREEC + bCol);
        __syncthreads();

#pragma unroll
        for (int k = 0; k < 8; k++) {
            float rM[8], rN[8];
#pragma unroll
            for (int i = 0; i < 8; i++) rM[i] = As[k][tRow * 8 + i];
#pragma unroll
            for (int j = 0; j < 8; j++) rN[j] = Bs[k][tCol * 8 + j];
#pragma unroll
            for (int i = 0; i < 8; i++)
#pragma unroll
                for (int j = 0; j < 8; j++) acc[i][j] += rM[i] * rN[j];
        }
        __syncthreads();
    }

    const float scale = 0.17677669529663687f;  // 32^-0.5
#pragma unroll
    for (int i = 0; i < 8; i++) {
        int row = cRow * 128 + tRow * 8 + i;   // token index
        int b = row / NTOK;
        int n = row - b * NTOK;
#pragma unroll
        for (int j = 0; j < 8; j++) {
            int c = cCol * 128 + tCol * 8 + j;
            float v = acc[i][j] + bias[c];
            int s   = c >> 9;        // which of q/k/v
            int rem = c & 511;
            int h  = rem >> 5;
            int dd = rem & 31;
            int idx = (((b * HEADS + h) * NTOK) + n) * HD + dd;
            if (s == 0)      g_q[idx] = v * scale;
            else if (s == 1) g_k[idx] = v;
            else             g_v[idx] = v;
        }
    }
}

// ---------------------------------------------------------------------------
// Kernel 2: per-(window, head) attention.  Grid = 2048*16 blocks, 256 threads.
//   S = q k^T + bias(rel_index, h); P = softmax(S); O = P v
// Writes g_att in (token, h*32+d) layout for the proj GEMM.
// ---------------------------------------------------------------------------
__global__ __launch_bounds__(256) void attn_kernel(const float* __restrict__ rpb,
                                                   const int* __restrict__ rel) {
    __shared__ float qs[NTOK * HD];
    __shared__ float ks[NTOK * HD];
    __shared__ float vs[NTOK * HD];
    __shared__ float S[NTOK][NTOK + 1];

    const int bh  = blockIdx.x;
    const int h   = bh & (HEADS - 1);
    const int b   = bh >> 4;
    const int tid = threadIdx.x;

    const int base = bh * NTOK * HD;
    for (int i = tid; i < NTOK * HD; i += 256) {
        qs[i] = g_q[base + i];
        ks[i] = g_k[base + i];
        vs[i] = g_v[base + i];
    }
    __syncthreads();

    // Scores + relative position bias
    for (int idx = tid; idx < NTOK * NTOK; idx += 256) {
        int n = idx / NTOK;
        int m = idx - n * NTOK;
        float s = 0.f;
#pragma unroll
        for (int d = 0; d < HD; d++) s += qs[n * HD + d] * ks[m * HD + d];
        s += rpb[rel[idx] * HEADS + h];
        S[n][m] = s;
    }
    __syncthreads();

    // Row softmax (one thread per row; 49 rows)
    if (tid < NTOK) {
        int n = tid;
        float mx = -1e30f;
        for (int m = 0; m < NTOK; m++) mx = fmaxf(mx, S[n][m]);
        float sum = 0.f;
        for (int m = 0; m < NTOK; m++) {
            float e = __expf(S[n][m] - mx);
            S[n][m] = e;
            sum += e;
        }
        float inv = 1.f / sum;
        for (int m = 0; m < NTOK; m++) S[n][m] *= inv;
    }
    __syncthreads();

    // O = P @ v, write in (token, channel) layout
    for (int idx = tid; idx < NTOK * HD; idx += 256) {
        int n = idx >> 5;
        int d = idx & 31;
        float o = 0.f;
#pragma unroll
        for (int m = 0; m < NTOK; m++) o += S[n][m] * vs[m * HD + d];
        g_att[(size_t)(b * NTOK + n) * DIM + h * HD + d] = o;
    }
}

// ---------------------------------------------------------------------------
// Kernel 3: projection GEMM.  out[100352,512] = g_att @ w_proj[512,512] + b
// Same tiling as kernel 1.  Grid: (512/128, 784) = (4, 784).
// ---------------------------------------------------------------------------
__global__ __launch_bounds__(256) void proj_gemm(const float* __restrict__ B,
                                                 const float* __restrict__ bias,
                                                 float* __restrict__ out) {
    __shared__ float As[8][128];
    __shared__ float Bs[8][128];

    const int tid  = threadIdx.x;
    const int cRow = blockIdx.y;
    const int cCol = blockIdx.x;

    const int tCol = tid & 15;
    const int tRow = tid >> 4;

    const int aRow = tid >> 1;
    const int aCol = (tid & 1) << 2;
    const int bRow = tid >> 5;
    const int bCol = (tid & 31) << 2;

    const float* Ab = g_att + (size_t)cRow * 128 * DIM;
    const float* Bb = B + cCol * 128;

    float acc[8][8];
#pragma unroll
    for (int i = 0; i < 8; i++)
#pragma unroll
        for (int j = 0; j < 8; j++) acc[i][j] = 0.f;

    for (int k0 = 0; k0 < DIM; k0 += 8) {
        float4 a4 = *(const float4*)(Ab + aRow * DIM + k0 + aCol);
        As[aCol + 0][aRow] = a4.x;
        As[aCol + 1][aRow] = a4.y;
        As[aCol + 2][aRow] = a4.z;
        As[aCol + 3][aRow] = a4.w;
        *(float4*)(&Bs[bRow][bCol]) =
            *(const float4*)(Bb + (size_t)(k0 + bRow) * DIM + bCol);
        __syncthreads();

#pragma unroll
        for (int k = 0; k < 8; k++) {
            float rM[8], rN[8];
#pragma unroll
            for (int i = 0; i < 8; i++) rM[i] = As[k][tRow * 8 + i];
#pragma unroll
            for (int j = 0; j < 8; j++) rN[j] = Bs[k][tCol * 8 + j];
#pragma unroll
            for (int i = 0; i < 8; i++)
#pragma unroll
                for (int j = 0; j < 8; j++) acc[i][j] += rM[i] * rN[j];
        }
        __syncthreads();
    }

#pragma unroll
    for (int i = 0; i < 8; i++) {
        int row = cRow * 128 + tRow * 8 + i;
#pragma unroll
        for (int j = 0; j < 8; j++) {
            int c = cCol * 128 + tCol * 8 + j;
            out[(size_t)row * DIM + c] = acc[i][j] + bias[c];
        }
    }
}

// ---------------------------------------------------------------------------
// Inputs (metadata order): x, w_qkv, b_qkv, rpb_table, w_proj, b_proj, rel_index
// Output: float32 [2048, 49, 512]
// ---------------------------------------------------------------------------
extern "C" void kernel_launch(void* const* d_in, const int* in_sizes, int n_in,
                              void* d_out, int out_size) {
    const float* x      = (const float*)d_in[0];
    const float* w_qkv  = (const float*)d_in[1];
    const float* b_qkv  = (const float*)d_in[2];
    const float* rpb    = (const float*)d_in[3];
    const float* w_proj = (const float*)d_in[4];
    const float* b_proj = (const float*)d_in[5];
    const int*   rel    = (const int*)d_in[6];
    float* out = (float*)d_out;

    dim3 grid1(THREEC / 128, M_TOT / 128);  // (12, 784)
    qkv_gemm<<<grid1, 256>>>(x, w_qkv, b_qkv);

    attn_kernel<<<BW * HEADS, 256>>>(rpb, rel);

    dim3 grid3(DIM / 128, M_TOT / 128);     // (4, 784)
    proj_gemm<<<grid3, 256>>>(w_proj, b_proj, out);
}

// round 11
// speedup vs baseline: 1.0654x; 1.0654x over previous
#include <cuda_runtime.h>
#include <cuda_bf16.h>

// Problem constants (Swin window attention)
#define WIN    7
#define NTOK   49
#define DIM    512
#define HEADS  16
#define HD     32
#define BW     2048
#define M_TOT  (BW * NTOK)   // 100352
#define THREEC 1536

#define BK     8
#define NCH    (DIM / BK)    // 64 K-chunks

// Scratch (allocation-free: __device__ globals)
__device__ float g_q[BW * HEADS * NTOK * HD];
__device__ float g_k[BW * HEADS * NTOK * HD];
__device__ float g_v[BW * HEADS * NTOK * HD];
__device__ float g_att[M_TOT * DIM];

// ---------------------------------------------------------------------------
// Kernel 1: QKV GEMM, double-buffered. C[100352,1536] = x @ w_qkv + b.
// 128x128 CTA tile, 256 threads, 8x8/thread, BK=8 two-deep SMEM pipeline
// with register-staged prefetch. Epilogue identical to round-1 (scatter to
// g_q scaled / g_k / g_v).
// ---------------------------------------------------------------------------
__global__ __launch_bounds__(256) void qkv_gemm_db(const float* __restrict__ A,
                                                   const float* __restrict__ B,
                                                   const float* __restrict__ bias) {
    __shared__ __align__(16) float As[2][BK][128];
    __shared__ __align__(16) float Bs[2][BK][128];

    const int tid  = threadIdx.x;
    const int tCol = tid & 15;
    const int tRow = tid >> 4;

    const int ar = tid >> 1;
    const int ac = (tid & 1) << 2;
    const int bk = tid >> 5;
    const int bc = (tid & 31) << 2;

    const float* Abase = A + (size_t)blockIdx.y * 128 * DIM + (size_t)ar * DIM + ac;
    const float* Bbase = B + (size_t)bk * THREEC + blockIdx.x * 128 + bc;

    float acc[8][8];
#pragma unroll
    for (int i = 0; i < 8; i++)
#pragma unroll
        for (int j = 0; j < 8; j++) acc[i][j] = 0.f;

    {
        float4 a = *(const float4*)(Abase);
        As[0][ac + 0][ar] = a.x;
        As[0][ac + 1][ar] = a.y;
        As[0][ac + 2][ar] = a.z;
        As[0][ac + 3][ar] = a.w;
        *(float4*)&Bs[0][bk][bc] = *(const float4*)(Bbase);
    }
    __syncthreads();

    for (int ch = 0; ch < NCH; ch++) {
        const int cb = ch & 1;
        const int nb = cb ^ 1;

        float4 pa, pb;
        if (ch + 1 < NCH) {
            pa = *(const float4*)(Abase + (ch + 1) * BK);
            pb = *(const float4*)(Bbase + (size_t)(ch + 1) * BK * THREEC);
        }

#pragma unroll
        for (int k = 0; k < BK; k++) {
            float rM[8], rN[8];
            float4 m0 = *(const float4*)&As[cb][k][tRow * 8];
            float4 m1 = *(const float4*)&As[cb][k][tRow * 8 + 4];
            float4 n0 = *(const float4*)&Bs[cb][k][tCol * 8];
            float4 n1 = *(const float4*)&Bs[cb][k][tCol * 8 + 4];
            rM[0] = m0.x; rM[1] = m0.y; rM[2] = m0.z; rM[3] = m0.w;
            rM[4] = m1.x; rM[5] = m1.y; rM[6] = m1.z; rM[7] = m1.w;
            rN[0] = n0.x; rN[1] = n0.y; rN[2] = n0.z; rN[3] = n0.w;
            rN[4] = n1.x; rN[5] = n1.y; rN[6] = n1.z; rN[7] = n1.w;
#pragma unroll
            for (int i = 0; i < 8; i++)
#pragma unroll
                for (int j = 0; j < 8; j++) acc[i][j] += rM[i] * rN[j];
        }

        if (ch + 1 < NCH) {
            As[nb][ac + 0][ar] = pa.x;
            As[nb][ac + 1][ar] = pa.y;
            As[nb][ac + 2][ar] = pa.z;
            As[nb][ac + 3][ar] = pa.w;
            *(float4*)&Bs[nb][bk][bc] = pb;
        }
        __syncthreads();
    }

    const float scale = 0.17677669529663687f;  // 32^-0.5
#pragma unroll
    for (int i = 0; i < 8; i++) {
        int row = blockIdx.y * 128 + tRow * 8 + i;
        int b = row / NTOK;
        int n = row - b * NTOK;
#pragma unroll
        for (int j = 0; j < 8; j++) {
            int c = blockIdx.x * 128 + tCol * 8 + j;
            float v = acc[i][j] + bias[c];
            int s   = c >> 9;
            int rem = c & 511;
            int h  = rem >> 5;
            int dd = rem & 31;
            int idx = (((b * HEADS + h) * NTOK) + n) * HD + dd;
            if (s == 0)      g_q[idx] = v * scale;
            else if (s == 1) g_k[idx] = v;
            else             g_v[idx] = v;
        }
    }
}

// ---------------------------------------------------------------------------
// Kernel 2: per-(window, head) attention — EXACT round-1 verified version.
// ---------------------------------------------------------------------------
__global__ __launch_bounds__(256) void attn_kernel(const float* __restrict__ rpb,
                                                   const int* __restrict__ rel) {
    __shared__ float qs[NTOK * HD];
    __shared__ float ks[NTOK * HD];
    __shared__ float vs[NTOK * HD];
    __shared__ float S[NTOK][NTOK + 1];

    const int bh  = blockIdx.x;
    const int h   = bh & (HEADS - 1);
    const int b   = bh >> 4;
    const int tid = threadIdx.x;

    const int base = bh * NTOK * HD;
    for (int i = tid; i < NTOK * HD; i += 256) {
        qs[i] = g_q[base + i];
        ks[i] = g_k[base + i];
        vs[i] = g_v[base + i];
    }
    __syncthreads();

    for (int idx = tid; idx < NTOK * NTOK; idx += 256) {
        int n = idx / NTOK;
        int m = idx - n * NTOK;
        float s = 0.f;
#pragma unroll
        for (int d = 0; d < HD; d++) s += qs[n * HD + d] * ks[m * HD + d];
        s += rpb[rel[idx] * HEADS + h];
        S[n][m] = s;
    }
    __syncthreads();

    if (tid < NTOK) {
        int n = tid;
        float mx = -1e30f;
        for (int m = 0; m < NTOK; m++) mx = fmaxf(mx, S[n][m]);
        float sum = 0.f;
        for (int m = 0; m < NTOK; m++) {
            float e = __expf(S[n][m] - mx);
            S[n][m] = e;
            sum += e;
        }
        float inv = 1.f / sum;
        for (int m = 0; m < NTOK; m++) S[n][m] *= inv;
    }
    __syncthreads();

    for (int idx = tid; idx < NTOK * HD; idx += 256) {
        int n = idx >> 5;
        int d = idx & 31;
        float o = 0.f;
#pragma unroll
        for (int m = 0; m < NTOK; m++) o += S[n][m] * vs[m * HD + d];
        g_att[(size_t)(b * NTOK + n) * DIM + h * HD + d] = o;
    }
}

// ---------------------------------------------------------------------------
// Kernel 3: projection GEMM, double-buffered. out = g_att @ w_proj + b.
// ---------------------------------------------------------------------------
__global__ __launch_bounds__(256) void proj_gemm_db(const float* __restrict__ B,
                                                    const float* __restrict__ bias,
                                                    float* __restrict__ out) {
    __shared__ __align__(16) float As[2][BK][128];
    __shared__ __align__(16) float Bs[2][BK][128];

    const int tid  = threadIdx.x;
    const int tCol = tid & 15;
    const int tRow = tid >> 4;

    const int ar = tid >> 1;
    const int ac = (tid & 1) << 2;
    const int bk = tid >> 5;
    const int bc = (tid & 31) << 2;

    const float* Abase = g_att + (size_t)blockIdx.y * 128 * DIM + (size_t)ar * DIM + ac;
    const float* Bbase = B + (size_t)bk * DIM + blockIdx.x * 128 + bc;

    float acc[8][8];
#pragma unroll
    for (int i = 0; i < 8; i++)
#pragma unroll
        for (int j = 0; j < 8; j++) acc[i][j] = 0.f;

    {
        float4 a = *(const float4*)(Abase);
        As[0][ac + 0][ar] = a.x;
        As[0][ac + 1][ar] = a.y;
        As[0][ac + 2][ar] = a.z;
        As[0][ac + 3][ar] = a.w;
        *(float4*)&Bs[0][bk][bc] = *(const float4*)(Bbase);
    }
    __syncthreads();

    for (int ch = 0; ch < NCH; ch++) {
        const int cb = ch & 1;
        const int nb = cb ^ 1;

        float4 pa, pb;
        if (ch + 1 < NCH) {
            pa = *(const float4*)(Abase + (ch + 1) * BK);
            pb = *(const float4*)(Bbase + (size_t)(ch + 1) * BK * DIM);
        }

#pragma unroll
        for (int k = 0; k < BK; k++) {
            float rM[8], rN[8];
            float4 m0 = *(const float4*)&As[cb][k][tRow * 8];
            float4 m1 = *(const float4*)&As[cb][k][tRow * 8 + 4];
            float4 n0 = *(const float4*)&Bs[cb][k][tCol * 8];
            float4 n1 = *(const float4*)&Bs[cb][k][tCol * 8 + 4];
            rM[0] = m0.x; rM[1] = m0.y; rM[2] = m0.z; rM[3] = m0.w;
            rM[4] = m1.x; rM[5] = m1.y; rM[6] = m1.z; rM[7] = m1.w;
            rN[0] = n0.x; rN[1] = n0.y; rN[2] = n0.z; rN[3] = n0.w;
            rN[4] = n1.x; rN[5] = n1.y; rN[6] = n1.z; rN[7] = n1.w;
#pragma unroll
            for (int i = 0; i < 8; i++)
#pragma unroll
                for (int j = 0; j < 8; j++) acc[i][j] += rM[i] * rN[j];
        }

        if (ch + 1 < NCH) {
            As[nb][ac + 0][ar] = pa.x;
            As[nb][ac + 1][ar] = pa.y;
            As[nb][ac + 2][ar] = pa.z;
            As[nb][ac + 3][ar] = pa.w;
            *(float4*)&Bs[nb][bk][bc] = pb;
        }
        __syncthreads();
    }

#pragma unroll
    for (int i = 0; i < 8; i++) {
        int row = blockIdx.y * 128 + tRow * 8 + i;
#pragma unroll
        for (int j = 0; j < 8; j++) {
            int c = blockIdx.x * 128 + tCol * 8 + j;
            out[(size_t)row * DIM + c] = acc[i][j] + bias[c];
        }
    }
}

// ---------------------------------------------------------------------------
// Inputs: x, w_qkv, b_qkv, rpb_table, w_proj, b_proj, rel_index
// ---------------------------------------------------------------------------
extern "C" void kernel_launch(void* const* d_in, const int* in_sizes, int n_in,
                              void* d_out, int out_size) {
    const float* x      = (const float*)d_in[0];
    const float* w_qkv  = (const float*)d_in[1];
    const float* b_qkv  = (const float*)d_in[2];
    const float* rpb    = (const float*)d_in[3];
    const float* w_proj = (const float*)d_in[4];
    const float* b_proj = (const float*)d_in[5];
    const int*   rel    = (const int*)d_in[6];
    float* out = (float*)d_out;

    dim3 grid1(THREEC / 128, M_TOT / 128);   // (12, 784)
    qkv_gemm_db<<<grid1, 256>>>(x, w_qkv, b_qkv);

    attn_kernel<<<BW * HEADS, 256>>>(rpb, rel);

    dim3 grid3(DIM / 128, M_TOT / 128);      // (4, 784)
    proj_gemm_db<<<grid3, 256>>>(w_proj, b_proj, out);
}

// round 13
// speedup vs baseline: 1.4954x; 1.4037x over previous
#include <cuda_runtime.h>
#include <cuda_bf16.h>

// Problem constants (Swin window attention)
#define WIN    7
#define NTOK   49
#define DIM    512
#define HEADS  16
#define HD     32
#define BW     2048
#define M_TOT  (BW * NTOK)   // 100352
#define THREEC 1536

#define BK     8
#define NCH    (DIM / BK)    // 64 K-chunks

// Scratch (allocation-free: __device__ globals)
__device__ float g_q[BW * HEADS * NTOK * HD];
__device__ float g_k[BW * HEADS * NTOK * HD];
__device__ float g_v[BW * HEADS * NTOK * HD];
__device__ float g_att[M_TOT * DIM];

// ---------------------------------------------------------------------------
// Kernel 1: QKV GEMM, double-buffered, phase-optimized smem layout.
// 128x128 CTA tile, 256 threads, 8x8/thread. Warp = 4x8 thread grid
// (tRow=(warp>>1)*4+(lane>>3), tCol=(warp&1)*8+(lane&7)). Bs stored permuted
// [wn(64)][half(32)][cc(4)] so each B fragment LDS.128 is one phase.
// ---------------------------------------------------------------------------
__global__ __launch_bounds__(256) void qkv_gemm_db(const float* __restrict__ A,
                                                   const float* __restrict__ B,
                                                   const float* __restrict__ bias) {
    __shared__ __align__(16) float As[2][BK][128];
    __shared__ __align__(16) float Bs[2][BK][128];   // permuted layout

    const int tid  = threadIdx.x;
    const int lane = tid & 31;
    const int warp = tid >> 5;
    const int tRow = (warp >> 1) * 4 + (lane >> 3);   // 0..15
    const int tCol = (warp & 1) * 8 + (lane & 7);     // 0..15
    const int wn   = warp & 1;
    const int cc   = lane & 7;

    const int ar = tid >> 1;
    const int ac = (tid & 1) << 2;
    const int bk = tid >> 5;
    const int bc = (tid & 31) << 2;
    // permuted store offset: block(64)*wn + half*32 + cc*4
    const int bpo = ((bc >> 6) << 6) | (((bc >> 2) & 1) << 5) | (((bc >> 3) & 7) << 2);

    const float* Abase = A + (size_t)blockIdx.y * 128 * DIM + (size_t)ar * DIM + ac;
    const float* Bbase = B + (size_t)bk * THREEC + blockIdx.x * 128 + bc;

    float acc[8][8];
#pragma unroll
    for (int i = 0; i < 8; i++)
#pragma unroll
        for (int j = 0; j < 8; j++) acc[i][j] = 0.f;

    {
        float4 a = *(const float4*)(Abase);
        As[0][ac + 0][ar] = a.x;
        As[0][ac + 1][ar] = a.y;
        As[0][ac + 2][ar] = a.z;
        As[0][ac + 3][ar] = a.w;
        *(float4*)&Bs[0][bk][bpo] = *(const float4*)(Bbase);
    }
    __syncthreads();

    for (int ch = 0; ch < NCH; ch++) {
        const int cb = ch & 1;
        const int nb = cb ^ 1;

        float4 pa, pb;
        if (ch + 1 < NCH) {
            pa = *(const float4*)(Abase + (ch + 1) * BK);
            pb = *(const float4*)(Bbase + (size_t)(ch + 1) * BK * THREEC);
        }

#pragma unroll
        for (int k = 0; k < BK; k++) {
            float rM[8], rN[8];
            float4 m0 = *(const float4*)&As[cb][k][tRow * 8];
            float4 m1 = *(const float4*)&As[cb][k][tRow * 8 + 4];
            float4 n0 = *(const float4*)&Bs[cb][k][wn * 64 + cc * 4];        // half 0
            float4 n1 = *(const float4*)&Bs[cb][k][wn * 64 + 32 + cc * 4];   // half 1
            rM[0] = m0.x; rM[1] = m0.y; rM[2] = m0.z; rM[3] = m0.w;
            rM[4] = m1.x; rM[5] = m1.y; rM[6] = m1.z; rM[7] = m1.w;
            rN[0] = n0.x; rN[1] = n0.y; rN[2] = n0.z; rN[3] = n0.w;
            rN[4] = n1.x; rN[5] = n1.y; rN[6] = n1.z; rN[7] = n1.w;
#pragma unroll
            for (int i = 0; i < 8; i++)
#pragma unroll
                for (int j = 0; j < 8; j++) acc[i][j] += rM[i] * rN[j];
        }

        if (ch + 1 < NCH) {
            As[nb][ac + 0][ar] = pa.x;
            As[nb][ac + 1][ar] = pa.y;
            As[nb][ac + 2][ar] = pa.z;
            As[nb][ac + 3][ar] = pa.w;
            *(float4*)&Bs[nb][bk][bpo] = pb;
        }
        __syncthreads();
    }

    const float scale = 0.17677669529663687f;  // 32^-0.5
#pragma unroll
    for (int i = 0; i < 8; i++) {
        int row = blockIdx.y * 128 + tRow * 8 + i;
        int b = row / NTOK;
        int n = row - b * NTOK;
#pragma unroll
        for (int j = 0; j < 8; j++) {
            int c = blockIdx.x * 128 + tCol * 8 + j;
            float v = acc[i][j] + bias[c];
            int s   = c >> 9;
            int rem = c & 511;
            int h  = rem >> 5;
            int dd = rem & 31;
            int idx = (((b * HEADS + h) * NTOK) + n) * HD + dd;
            if (s == 0)      g_q[idx] = v * scale;
            else if (s == 1) g_k[idx] = v;
            else             g_v[idx] = v;
        }
    }
}

// ---------------------------------------------------------------------------
// Kernel 2: attention. Transposed-K score phase (conflict-free), 2n x 4m
// register tiling, warp-per-row shuffle softmax, float4 PV.
// ---------------------------------------------------------------------------
__global__ __launch_bounds__(256) void attn_kernel(const float* __restrict__ rpb,
                                                   const int* __restrict__ rel) {
    __shared__ float qs[NTOK * HD];              // [n][d]
    __shared__ __align__(16) float kst[HD][52];  // [d][m], pad 52 (16B aligned rows)
    __shared__ float vs[NTOK * HD];              // [m][d]
    __shared__ float S[NTOK][52];

    const int bh  = blockIdx.x;
    const int h   = bh & (HEADS - 1);
    const int b   = bh >> 4;
    const int tid = threadIdx.x;

    const int base = bh * NTOK * HD;
    for (int i = tid; i < NTOK * HD; i += 256) {
        int n = i >> 5;
        int d = i & 31;
        qs[i] = g_q[base + i];
        kst[d][n] = g_k[base + i];
        vs[i] = g_v[base + i];
    }
    // zero the kst pad columns 49..51
    if (tid < 128) {
        int d = tid >> 2;
        int c = tid & 3;
        if (c < 3) kst[d][49 + c] = 0.f;
    }
    __syncthreads();

    // ---- scores: 25 n-tiles x 13 m-tiles, 2n x 4m per tile ----
    for (int t = tid; t < 325; t += 256) {
        int n0 = (t / 13) * 2;
        int m0 = (t % 13) * 4;
        bool n1ok = (n0 + 1 < NTOK);
        int n1 = n1ok ? n0 + 1 : n0;
        float a0[4] = {0.f, 0.f, 0.f, 0.f};
        float a1[4] = {0.f, 0.f, 0.f, 0.f};
#pragma unroll
        for (int d = 0; d < HD; d++) {
            float q0 = qs[n0 * HD + d];
            float q1 = qs[n1 * HD + d];
            float4 k4 = *(const float4*)&kst[d][m0];
            a0[0] += q0 * k4.x; a0[1] += q0 * k4.y;
            a0[2] += q0 * k4.z; a0[3] += q0 * k4.w;
            a1[0] += q1 * k4.x; a1[1] += q1 * k4.y;
            a1[2] += q1 * k4.z; a1[3] += q1 * k4.w;
        }
#pragma unroll
        for (int j = 0; j < 4; j++) {
            int m = m0 + j;
            if (m < NTOK) {
                S[n0][m] = a0[j] + rpb[rel[n0 * NTOK + m] * HEADS + h];
                if (n1ok)
                    S[n0 + 1][m] = a1[j] + rpb[rel[(n0 + 1) * NTOK + m] * HEADS + h];
            }
        }
    }
    __syncthreads();

    // ---- softmax: warp per row ----
    {
        const int warp = tid >> 5;
        const int lane = tid & 31;
        for (int n = warp; n < NTOK; n += 8) {
            float v0 = S[n][lane];
            bool hi = (lane + 32 < NTOK);
            float v1 = hi ? S[n][lane + 32] : -1e30f;
            float mx = fmaxf(v0, v1);
#pragma unroll
            for (int o = 16; o; o >>= 1) mx = fmaxf(mx, __shfl_xor_sync(0xffffffffu, mx, o));
            float e0 = __expf(v0 - mx);
            float e1 = hi ? __expf(v1 - mx) : 0.f;
            float sum = e0 + e1;
#pragma unroll
            for (int o = 16; o; o >>= 1) sum += __shfl_xor_sync(0xffffffffu, sum, o);
            float inv = 1.f / sum;
            S[n][lane] = e0 * inv;
            if (hi) S[n][lane + 32] = e1 * inv;
        }
    }
    __syncthreads();

    // ---- PV: 49 n x 8 d4-groups = 392 work items, float4 over d ----
    for (int w = tid; w < NTOK * 8; w += 256) {
        int n  = w >> 3;
        int d0 = (w & 7) << 2;
        float4 acc = make_float4(0.f, 0.f, 0.f, 0.f);
        for (int m = 0; m < NTOK; m++) {
            float s = S[n][m];
            float4 v = *(const float4*)&vs[m * HD + d0];
            acc.x += s * v.x; acc.y += s * v.y;
            acc.z += s * v.z; acc.w += s * v.w;
        }
        *(float4*)&g_att[(size_t)(b * NTOK + n) * DIM + h * HD + d0] = acc;
    }
}

// ---------------------------------------------------------------------------
// Kernel 3: projection GEMM — same phase-optimized structure as kernel 1.
// ---------------------------------------------------------------------------
__global__ __launch_bounds__(256) void proj_gemm_db(const float* __restrict__ B,
                                                    const float* __restrict__ bias,
                                                    float* __restrict__ out) {
    __shared__ __align__(16) float As[2][BK][128];
    __shared__ __align__(16) float Bs[2][BK][128];   // permuted layout

    const int tid  = threadIdx.x;
    const int lane = tid & 31;
    const int warp = tid >> 5;
    const int tRow = (warp >> 1) * 4 + (lane >> 3);
    const int tCol = (warp & 1) * 8 + (lane & 7);
    const int wn   = warp & 1;
    const int cc   = lane & 7;

    const int ar = tid >> 1;
    const int ac = (tid & 1) << 2;
    const int bk = tid >> 5;
    const int bc = (tid & 31) << 2;
    const int bpo = ((bc >> 6) << 6) | (((bc >> 2) & 1) << 5) | (((bc >> 3) & 7) << 2);

    const float* Abase = g_att + (size_t)blockIdx.y * 128 * DIM + (size_t)ar * DIM + ac;
    const float* Bbase = B + (size_t)bk * DIM + blockIdx.x * 128 + bc;

    float acc[8][8];
#pragma unroll
    for (int i = 0; i < 8; i++)
#pragma unroll
        for (int j = 0; j < 8; j++) acc[i][j] = 0.f;

    {
        float4 a = *(const float4*)(Abase);
        As[0][ac + 0][ar] = a.x;
        As[0][ac + 1][ar] = a.y;
        As[0][ac + 2][ar] = a.z;
        As[0][ac + 3][ar] = a.w;
        *(float4*)&Bs[0][bk][bpo] = *(const float4*)(Bbase);
    }
    __syncthreads();

    for (int ch = 0; ch < NCH; ch++) {
        const int cb = ch & 1;
        const int nb = cb ^ 1;

        float4 pa, pb;
        if (ch + 1 < NCH) {
            pa = *(const float4*)(Abase + (ch + 1) * BK);
            pb = *(const float4*)(Bbase + (size_t)(ch + 1) * BK * DIM);
        }

#pragma unroll
        for (int k = 0; k < BK; k++) {
            float rM[8], rN[8];
            float4 m0 = *(const float4*)&As[cb][k][tRow * 8];
            float4 m1 = *(const float4*)&As[cb][k][tRow * 8 + 4];
            float4 n0 = *(const float4*)&Bs[cb][k][wn * 64 + cc * 4];
            float4 n1 = *(const float4*)&Bs[cb][k][wn * 64 + 32 + cc * 4];
            rM[0] = m0.x; rM[1] = m0.y; rM[2] = m0.z; rM[3] = m0.w;
            rM[4] = m1.x; rM[5] = m1.y; rM[6] = m1.z; rM[7] = m1.w;
            rN[0] = n0.x; rN[1] = n0.y; rN[2] = n0.z; rN[3] = n0.w;
            rN[4] = n1.x; rN[5] = n1.y; rN[6] = n1.z; rN[7] = n1.w;
#pragma unroll
            for (int i = 0; i < 8; i++)
#pragma unroll
                for (int j = 0; j < 8; j++) acc[i][j] += rM[i] * rN[j];
        }

        if (ch + 1 < NCH) {
            As[nb][ac + 0][ar] = pa.x;
            As[nb][ac + 1][ar] = pa.y;
            As[nb][ac + 2][ar] = pa.z;
            As[nb][ac + 3][ar] = pa.w;
            *(float4*)&Bs[nb][bk][bpo] = pb;
        }
        __syncthreads();
    }

#pragma unroll
    for (int i = 0; i < 8; i++) {
        int row = blockIdx.y * 128 + tRow * 8 + i;
#pragma unroll
        for (int j = 0; j < 8; j++) {
            int c = blockIdx.x * 128 + tCol * 8 + j;
            out[(size_t)row * DIM + c] = acc[i][j] + bias[c];
        }
    }
}

// ---------------------------------------------------------------------------
// Inputs: x, w_qkv, b_qkv, rpb_table, w_proj, b_proj, rel_index
// ---------------------------------------------------------------------------
extern "C" void kernel_launch(void* const* d_in, const int* in_sizes, int n_in,
                              void* d_out, int out_size) {
    const float* x      = (const float*)d_in[0];
    const float* w_qkv  = (const float*)d_in[1];
    const float* b_qkv  = (const float*)d_in[2];
    const float* rpb    = (const float*)d_in[3];
    const float* w_proj = (const float*)d_in[4];
    const float* b_proj = (const float*)d_in[5];
    const int*   rel    = (const int*)d_in[6];
    float* out = (float*)d_out;

    dim3 grid1(THREEC / 128, M_TOT / 128);   // (12, 784)
    qkv_gemm_db<<<grid1, 256>>>(x, w_qkv, b_qkv);

    attn_kernel<<<BW * HEADS, 256>>>(rpb, rel);

    dim3 grid3(DIM / 128, M_TOT / 128);      // (4, 784)
    proj_gemm_db<<<grid3, 256>>>(w_proj, b_proj, out);
}

// round 14
// speedup vs baseline: 1.5166x; 1.0141x over previous
#include <cuda_runtime.h>
#include <cuda_bf16.h>

// Problem constants (Swin window attention)
#define WIN    7
#define NTOK   49
#define DIM    512
#define HEADS  16
#define HD     32
#define BW     2048
#define M_TOT  (BW * NTOK)   // 100352
#define THREEC 1536

#define BK     16
#define NCH    (DIM / BK)    // 32 K-chunks

// Scratch (allocation-free: __device__ globals)
__device__ float g_q[BW * HEADS * NTOK * HD];
__device__ float g_k[BW * HEADS * NTOK * HD];
__device__ float g_v[BW * HEADS * NTOK * HD];
__device__ float g_att[M_TOT * DIM];

// ---------------------------------------------------------------------------
// Kernel 1: QKV GEMM, double-buffered BK=16, phase-optimized smem layout.
// 128x128 CTA tile, 256 threads, 8x8/thread. Warp = 4x8 thread grid,
// Bs permuted [wn(64)][half(32)][cc(4)] -> each B fragment LDS.128 = 1 phase.
// One barrier per 16 k-steps (halved vs BK=8).
// ---------------------------------------------------------------------------
__global__ __launch_bounds__(256) void qkv_gemm_db(const float* __restrict__ A,
                                                   const float* __restrict__ B,
                                                   const float* __restrict__ bias) {
    __shared__ __align__(16) float As[2][BK][128];   // 16KB
    __shared__ __align__(16) float Bs[2][BK][128];   // 16KB, permuted

    const int tid  = threadIdx.x;
    const int lane = tid & 31;
    const int warp = tid >> 5;
    const int tRow = (warp >> 1) * 4 + (lane >> 3);   // 0..15
    const int tCol = (warp & 1) * 8 + (lane & 7);     // 0..15
    const int wn   = warp & 1;
    const int cc   = lane & 7;

    const int ar = tid >> 1;            // A row 0..127
    const int ac = (tid & 1) << 3;      // A col 0 or 8
    const int bk = tid >> 4;            // B k-row 0..15
    const int bc = (tid & 15) << 3;     // B col 0..120 (mult of 8)
    // permuted store offset (bc%8==0 -> half bit = 0); +4 goes to +32
    const int bpo = ((bc >> 6) << 6) | (((bc >> 3) & 7) << 2);

    const float* Abase = A + (size_t)blockIdx.y * 128 * DIM + (size_t)ar * DIM + ac;
    const float* Bbase = B + (size_t)bk * THREEC + blockIdx.x * 128 + bc;

    float acc[8][8];
#pragma unroll
    for (int i = 0; i < 8; i++)
#pragma unroll
        for (int j = 0; j < 8; j++) acc[i][j] = 0.f;

    {
        float4 a0 = *(const float4*)(Abase);
        float4 a1 = *(const float4*)(Abase + 4);
        As[0][ac + 0][ar] = a0.x; As[0][ac + 1][ar] = a0.y;
        As[0][ac + 2][ar] = a0.z; As[0][ac + 3][ar] = a0.w;
        As[0][ac + 4][ar] = a1.x; As[0][ac + 5][ar] = a1.y;
        As[0][ac + 6][ar] = a1.z; As[0][ac + 7][ar] = a1.w;
        *(float4*)&Bs[0][bk][bpo]      = *(const float4*)(Bbase);
        *(float4*)&Bs[0][bk][bpo + 32] = *(const float4*)(Bbase + 4);
    }
    __syncthreads();

    for (int ch = 0; ch < NCH; ch++) {
        const int cb = ch & 1;
        const int nb = cb ^ 1;

        float4 pa0, pa1, pb0, pb1;
        if (ch + 1 < NCH) {
            pa0 = *(const float4*)(Abase + (ch + 1) * BK);
            pa1 = *(const float4*)(Abase + (ch + 1) * BK + 4);
            pb0 = *(const float4*)(Bbase + (size_t)(ch + 1) * BK * THREEC);
            pb1 = *(const float4*)(Bbase + (size_t)(ch + 1) * BK * THREEC + 4);
        }

#pragma unroll
        for (int k = 0; k < BK; k++) {
            float rM[8], rN[8];
            float4 m0 = *(const float4*)&As[cb][k][tRow * 8];
            float4 m1 = *(const float4*)&As[cb][k][tRow * 8 + 4];
            float4 n0 = *(const float4*)&Bs[cb][k][wn * 64 + cc * 4];
            float4 n1 = *(const float4*)&Bs[cb][k][wn * 64 + 32 + cc * 4];
            rM[0] = m0.x; rM[1] = m0.y; rM[2] = m0.z; rM[3] = m0.w;
            rM[4] = m1.x; rM[5] = m1.y; rM[6] = m1.z; rM[7] = m1.w;
            rN[0] = n0.x; rN[1] = n0.y; rN[2] = n0.z; rN[3] = n0.w;
            rN[4] = n1.x; rN[5] = n1.y; rN[6] = n1.z; rN[7] = n1.w;
#pragma unroll
            for (int i = 0; i < 8; i++)
#pragma unroll
                for (int j = 0; j < 8; j++) acc[i][j] += rM[i] * rN[j];
        }

        if (ch + 1 < NCH) {
            As[nb][ac + 0][ar] = pa0.x; As[nb][ac + 1][ar] = pa0.y;
            As[nb][ac + 2][ar] = pa0.z; As[nb][ac + 3][ar] = pa0.w;
            As[nb][ac + 4][ar] = pa1.x; As[nb][ac + 5][ar] = pa1.y;
            As[nb][ac + 6][ar] = pa1.z; As[nb][ac + 7][ar] = pa1.w;
            *(float4*)&Bs[nb][bk][bpo]      = pb0;
            *(float4*)&Bs[nb][bk][bpo + 32] = pb1;
        }
        __syncthreads();
    }

    const float scale = 0.17677669529663687f;  // 32^-0.5
#pragma unroll
    for (int i = 0; i < 8; i++) {
        int row = blockIdx.y * 128 + tRow * 8 + i;
        int b = row / NTOK;
        int n = row - b * NTOK;
#pragma unroll
        for (int j = 0; j < 8; j++) {
            int c = blockIdx.x * 128 + tCol * 8 + j;
            float v = acc[i][j] + bias[c];
            int s   = c >> 9;
            int rem = c & 511;
            int h  = rem >> 5;
            int dd = rem & 31;
            int idx = (((b * HEADS + h) * NTOK) + n) * HD + dd;
            if (s == 0)      g_q[idx] = v * scale;
            else if (s == 1) g_k[idx] = v;
            else             g_v[idx] = v;
        }
    }
}

// ---------------------------------------------------------------------------
// Kernel 2: attention. float4-q score phase (6 LDS per 32 FFMA), transposed-K,
// warp-per-row shuffle softmax, PV with float4 S and 2n x 4d tiles.
// ---------------------------------------------------------------------------
__global__ __launch_bounds__(256) void attn_kernel(const float* __restrict__ rpb,
                                                   const int* __restrict__ rel) {
    __shared__ __align__(16) float qs[NTOK * HD];    // [n][d]
    __shared__ __align__(16) float kst[HD][52];      // [d][m], pad 52
    __shared__ __align__(16) float vs[NTOK * HD];    // [m][d]
    __shared__ __align__(16) float S[NTOK][52];

    const int bh  = blockIdx.x;
    const int h   = bh & (HEADS - 1);
    const int b   = bh >> 4;
    const int tid = threadIdx.x;

    const int base = bh * NTOK * HD;
    for (int i = tid; i < NTOK * HD; i += 256) {
        int n = i >> 5;
        int d = i & 31;
        qs[i] = g_q[base + i];
        kst[d][n] = g_k[base + i];
        vs[i] = g_v[base + i];
    }
    if (tid < 128) {                      // zero kst pad cols 49..51
        int d = tid >> 2;
        int c = tid & 3;
        if (c < 3) kst[d][49 + c] = 0.f;
    }
    __syncthreads();

    // ---- scores: 25 n-tiles x 13 m-tiles, 2n x 4m, float4 q ----
    for (int t = tid; t < 325; t += 256) {
        int n0 = (t / 13) * 2;
        int m0 = (t % 13) * 4;
        bool n1ok = (n0 + 1 < NTOK);
        int n1 = n1ok ? n0 + 1 : n0;
        float a0[4] = {0.f, 0.f, 0.f, 0.f};
        float a1[4] = {0.f, 0.f, 0.f, 0.f};
#pragma unroll
        for (int d0 = 0; d0 < HD; d0 += 4) {
            float4 qa = *(const float4*)&qs[n0 * HD + d0];
            float4 qb = *(const float4*)&qs[n1 * HD + d0];
            float4 k0 = *(const float4*)&kst[d0 + 0][m0];
            float4 k1 = *(const float4*)&kst[d0 + 1][m0];
            float4 k2 = *(const float4*)&kst[d0 + 2][m0];
            float4 k3 = *(const float4*)&kst[d0 + 3][m0];
            a0[0] += qa.x * k0.x + qa.y * k1.x + qa.z * k2.x + qa.w * k3.x;
            a0[1] += qa.x * k0.y + qa.y * k1.y + qa.z * k2.y + qa.w * k3.y;
            a0[2] += qa.x * k0.z + qa.y * k1.z + qa.z * k2.z + qa.w * k3.z;
            a0[3] += qa.x * k0.w + qa.y * k1.w + qa.z * k2.w + qa.w * k3.w;
            a1[0] += qb.x * k0.x + qb.y * k1.x + qb.z * k2.x + qb.w * k3.x;
            a1[1] += qb.x * k0.y + qb.y * k1.y + qb.z * k2.y + qb.w * k3.y;
            a1[2] += qb.x * k0.z + qb.y * k1.z + qb.z * k2.z + qb.w * k3.z;
            a1[3] += qb.x * k0.w + qb.y * k1.w + qb.z * k2.w + qb.w * k3.w;
        }
#pragma unroll
        for (int j = 0; j < 4; j++) {
            int m = m0 + j;
            if (m < NTOK) {
                S[n0][m] = a0[j] + rpb[rel[n0 * NTOK + m] * HEADS + h];
                if (n1ok)
                    S[n0 + 1][m] = a1[j] + rpb[rel[(n0 + 1) * NTOK + m] * HEADS + h];
            }
        }
    }
    __syncthreads();

    // ---- softmax: warp per row ----
    {
        const int warp = tid >> 5;
        const int lane = tid & 31;
        for (int n = warp; n < NTOK; n += 8) {
            float v0 = S[n][lane];
            bool hi = (lane + 32 < NTOK);
            float v1 = hi ? S[n][lane + 32] : -1e30f;
            float mx = fmaxf(v0, v1);
#pragma unroll
            for (int o = 16; o; o >>= 1) mx = fmaxf(mx, __shfl_xor_sync(0xffffffffu, mx, o));
            float e0 = __expf(v0 - mx);
            float e1 = hi ? __expf(v1 - mx) : 0.f;
            float sum = e0 + e1;
#pragma unroll
            for (int o = 16; o; o >>= 1) sum += __shfl_xor_sync(0xffffffffu, sum, o);
            float inv = 1.f / sum;
            S[n][lane] = e0 * inv;
            if (hi) S[n][lane + 32] = e1 * inv;
        }
    }
    __syncthreads();

    // ---- PV: 25 n-tiles x 8 d4-groups = 200 items, 2n x 4d, float4 S ----
    if (tid < 200) {
        int n0 = (tid >> 3) * 2;
        int d0 = (tid & 7) << 2;
        bool n1ok = (n0 + 1 < NTOK);
        int n1 = n1ok ? n0 + 1 : n0;
        float4 acc0 = make_float4(0.f, 0.f, 0.f, 0.f);
        float4 acc1 = acc0;
#pragma unroll 4
        for (int m4 = 0; m4 < 48; m4 += 4) {
            float4 s0 = *(const float4*)&S[n0][m4];
            float4 s1 = *(const float4*)&S[n1][m4];
            float4 v0 = *(const float4*)&vs[(m4 + 0) * HD + d0];
            float4 v1 = *(const float4*)&vs[(m4 + 1) * HD + d0];
            float4 v2 = *(const float4*)&vs[(m4 + 2) * HD + d0];
            float4 v3 = *(const float4*)&vs[(m4 + 3) * HD + d0];
            acc0.x += s0.x * v0.x + s0.y * v1.x + s0.z * v2.x + s0.w * v3.x;
            acc0.y += s0.x * v0.y + s0.y * v1.y + s0.z * v2.y + s0.w * v3.y;
            acc0.z += s0.x * v0.z + s0.y * v1.z + s0.z * v2.z + s0.w * v3.z;
            acc0.w += s0.x * v0.w + s0.y * v1.w + s0.z * v2.w + s0.w * v3.w;
            acc1.x += s1.x * v0.x + s1.y * v1.x + s1.z * v2.x + s1.w * v3.x;
            acc1.y += s1.x * v0.y + s1.y * v1.y + s1.z * v2.y + s1.w * v3.y;
            acc1.z += s1.x * v0.z + s1.y * v1.z + s1.z * v2.z + s1.w * v3.z;
            acc1.w += s1.x * v0.w + s1.y * v1.w + s1.z * v2.w + s1.w * v3.w;
        }
        {   // m = 48 tail
            float s0 = S[n0][48];
            float s1 = S[n1][48];
            float4 v = *(const float4*)&vs[48 * HD + d0];
            acc0.x += s0 * v.x; acc0.y += s0 * v.y;
            acc0.z += s0 * v.z; acc0.w += s0 * v.w;
            acc1.x += s1 * v.x; acc1.y += s1 * v.y;
            acc1.z += s1 * v.z; acc1.w += s1 * v.w;
        }
        float* o0 = g_att + (size_t)(b * NTOK + n0) * DIM + h * HD + d0;
        *(float4*)o0 = acc0;
        if (n1ok) *(float4*)(o0 + DIM) = acc1;
    }
}

// ---------------------------------------------------------------------------
// Kernel 3: projection GEMM — same BK=16 structure as kernel 1.
// ---------------------------------------------------------------------------
__global__ __launch_bounds__(256) void proj_gemm_db(const float* __restrict__ B,
                                                    const float* __restrict__ bias,
                                                    float* __restrict__ out) {
    __shared__ __align__(16) float As[2][BK][128];
    __shared__ __align__(16) float Bs[2][BK][128];

    const int tid  = threadIdx.x;
    const int lane = tid & 31;
    const int warp = tid >> 5;
    const int tRow = (warp >> 1) * 4 + (lane >> 3);
    const int tCol = (warp & 1) * 8 + (lane & 7);
    const int wn   = warp & 1;
    const int cc   = lane & 7;

    const int ar = tid >> 1;
    const int ac = (tid & 1) << 3;
    const int bk = tid >> 4;
    const int bc = (tid & 15) << 3;
    const int bpo = ((bc >> 6) << 6) | (((bc >> 3) & 7) << 2);

    const float* Abase = g_att + (size_t)blockIdx.y * 128 * DIM + (size_t)ar * DIM + ac;
    const float* Bbase = B + (size_t)bk * DIM + blockIdx.x * 128 + bc;

    float acc[8][8];
#pragma unroll
    for (int i = 0; i < 8; i++)
#pragma unroll
        for (int j = 0; j < 8; j++) acc[i][j] = 0.f;

    {
        float4 a0 = *(const float4*)(Abase);
        float4 a1 = *(const float4*)(Abase + 4);
        As[0][ac + 0][ar] = a0.x; As[0][ac + 1][ar] = a0.y;
        As[0][ac + 2][ar] = a0.z; As[0][ac + 3][ar] = a0.w;
        As[0][ac + 4][ar] = a1.x; As[0][ac + 5][ar] = a1.y;
        As[0][ac + 6][ar] = a1.z; As[0][ac + 7][ar] = a1.w;
        *(float4*)&Bs[0][bk][bpo]      = *(const float4*)(Bbase);
        *(float4*)&Bs[0][bk][bpo + 32] = *(const float4*)(Bbase + 4);
    }
    __syncthreads();

    for (int ch = 0; ch < NCH; ch++) {
        const int cb = ch & 1;
        const int nb = cb ^ 1;

        float4 pa0, pa1, pb0, pb1;
        if (ch + 1 < NCH) {
            pa0 = *(const float4*)(Abase + (ch + 1) * BK);
            pa1 = *(const float4*)(Abase + (ch + 1) * BK + 4);
            pb0 = *(const float4*)(Bbase + (size_t)(ch + 1) * BK * DIM);
            pb1 = *(const float4*)(Bbase + (size_t)(ch + 1) * BK * DIM + 4);
        }

#pragma unroll
        for (int k = 0; k < BK; k++) {
            float rM[8], rN[8];
            float4 m0 = *(const float4*)&As[cb][k][tRow * 8];
            float4 m1 = *(const float4*)&As[cb][k][tRow * 8 + 4];
            float4 n0 = *(const float4*)&Bs[cb][k][wn * 64 + cc * 4];
            float4 n1 = *(const float4*)&Bs[cb][k][wn * 64 + 32 + cc * 4];
            rM[0] = m0.x; rM[1] = m0.y; rM[2] = m0.z; rM[3] = m0.w;
            rM[4] = m1.x; rM[5] = m1.y; rM[6] = m1.z; rM[7] = m1.w;
            rN[0] = n0.x; rN[1] = n0.y; rN[2] = n0.z; rN[3] = n0.w;
            rN[4] = n1.x; rN[5] = n1.y; rN[6] = n1.z; rN[7] = n1.w;
#pragma unroll
            for (int i = 0; i < 8; i++)
#pragma unroll
                for (int j = 0; j < 8; j++) acc[i][j] += rM[i] * rN[j];
        }

        if (ch + 1 < NCH) {
            As[nb][ac + 0][ar] = pa0.x; As[nb][ac + 1][ar] = pa0.y;
            As[nb][ac + 2][ar] = pa0.z; As[nb][ac + 3][ar] = pa0.w;
            As[nb][ac + 4][ar] = pa1.x; As[nb][ac + 5][ar] = pa1.y;
            As[nb][ac + 6][ar] = pa1.z; As[nb][ac + 7][ar] = pa1.w;
            *(float4*)&Bs[nb][bk][bpo]      = pb0;
            *(float4*)&Bs[nb][bk][bpo + 32] = pb1;
        }
        __syncthreads();
    }

#pragma unroll
    for (int i = 0; i < 8; i++) {
        int row = blockIdx.y * 128 + tRow * 8 + i;
#pragma unroll
        for (int j = 0; j < 8; j++) {
            int c = blockIdx.x * 128 + tCol * 8 + j;
            out[(size_t)row * DIM + c] = acc[i][j] + bias[c];
        }
    }
}

// ---------------------------------------------------------------------------
// Inputs: x, w_qkv, b_qkv, rpb_table, w_proj, b_proj, rel_index
// ---------------------------------------------------------------------------
extern "C" void kernel_launch(void* const* d_in, const int* in_sizes, int n_in,
                              void* d_out, int out_size) {
    const float* x      = (const float*)d_in[0];
    const float* w_qkv  = (const float*)d_in[1];
    const float* b_qkv  = (const float*)d_in[2];
    const float* rpb    = (const float*)d_in[3];
    const float* w_proj = (const float*)d_in[4];
    const float* b_proj = (const float*)d_in[5];
    const int*   rel    = (const int*)d_in[6];
    float* out = (float*)d_out;

    dim3 grid1(THREEC / 128, M_TOT / 128);   // (12, 784)
    qkv_gemm_db<<<grid1, 256>>>(x, w_qkv, b_qkv);

    attn_kernel<<<BW * HEADS, 256>>>(rpb, rel);

    dim3 grid3(DIM / 128, M_TOT / 128);      // (4, 784)
    proj_gemm_db<<<grid3, 256>>>(w_proj, b_proj, out);
}

// round 15
// speedup vs baseline: 1.6912x; 1.1151x over previous
#include <cuda_runtime.h>
#include <cuda_bf16.h>

// Problem constants (Swin window attention)
#define WIN    7
#define NTOK   49
#define DIM    512
#define HEADS  16
#define HD     32
#define BW     2048
#define M_TOT  (BW * NTOK)   // 100352
#define THREEC 1536
#define NSQ    (NTOK * NTOK) // 2401

#define BK     16
#define NCH    (DIM / BK)    // 32 K-chunks

// Scratch (allocation-free: __device__ globals)
__device__ float g_q[BW * HEADS * NTOK * HD];
__device__ float g_k[BW * HEADS * NTOK * HD];
__device__ float g_v[BW * HEADS * NTOK * HD];
__device__ float g_att[M_TOT * DIM];
__device__ float g_bias[HEADS * NSQ];      // precomputed rpb[rel[nm]*16+h]

// ---------------------------------------------------------------------------
// Kernel 0: bias precompute. g_bias[h][nm] = rpb[rel[nm]*HEADS + h].
// 38416 elements; replaces 32768x2401 divergent 2-level gathers in attention.
// ---------------------------------------------------------------------------
__global__ void bias_precompute(const float* __restrict__ rpb,
                                const int* __restrict__ rel) {
    int t = blockIdx.x * 256 + threadIdx.x;
    if (t < HEADS * NSQ) {
        int h  = t / NSQ;
        int nm = t - h * NSQ;
        g_bias[t] = rpb[rel[nm] * HEADS + h];
    }
}

// ---------------------------------------------------------------------------
// Kernel 1: QKV GEMM, double-buffered BK=16, phase-optimized smem layout,
// vectorized (STG.128) scatter epilogue.
// ---------------------------------------------------------------------------
__global__ __launch_bounds__(256) void qkv_gemm_db(const float* __restrict__ A,
                                                   const float* __restrict__ B,
                                                   const float* __restrict__ bias) {
    __shared__ __align__(16) float As[2][BK][128];
    __shared__ __align__(16) float Bs[2][BK][128];   // permuted

    const int tid  = threadIdx.x;
    const int lane = tid & 31;
    const int warp = tid >> 5;
    const int tRow = (warp >> 1) * 4 + (lane >> 3);
    const int tCol = (warp & 1) * 8 + (lane & 7);
    const int wn   = warp & 1;
    const int cc   = lane & 7;

    const int ar = tid >> 1;
    const int ac = (tid & 1) << 3;
    const int bk = tid >> 4;
    const int bc = (tid & 15) << 3;
    const int bpo = ((bc >> 6) << 6) | (((bc >> 3) & 7) << 2);

    const float* Abase = A + (size_t)blockIdx.y * 128 * DIM + (size_t)ar * DIM + ac;
    const float* Bbase = B + (size_t)bk * THREEC + blockIdx.x * 128 + bc;

    float acc[8][8];
#pragma unroll
    for (int i = 0; i < 8; i++)
#pragma unroll
        for (int j = 0; j < 8; j++) acc[i][j] = 0.f;

    {
        float4 a0 = *(const float4*)(Abase);
        float4 a1 = *(const float4*)(Abase + 4);
        As[0][ac + 0][ar] = a0.x; As[0][ac + 1][ar] = a0.y;
        As[0][ac + 2][ar] = a0.z; As[0][ac + 3][ar] = a0.w;
        As[0][ac + 4][ar] = a1.x; As[0][ac + 5][ar] = a1.y;
        As[0][ac + 6][ar] = a1.z; As[0][ac + 7][ar] = a1.w;
        *(float4*)&Bs[0][bk][bpo]      = *(const float4*)(Bbase);
        *(float4*)&Bs[0][bk][bpo + 32] = *(const float4*)(Bbase + 4);
    }
    __syncthreads();

    for (int ch = 0; ch < NCH; ch++) {
        const int cb = ch & 1;
        const int nb = cb ^ 1;

        float4 pa0, pa1, pb0, pb1;
        if (ch + 1 < NCH) {
            pa0 = *(const float4*)(Abase + (ch + 1) * BK);
            pa1 = *(const float4*)(Abase + (ch + 1) * BK + 4);
            pb0 = *(const float4*)(Bbase + (size_t)(ch + 1) * BK * THREEC);
            pb1 = *(const float4*)(Bbase + (size_t)(ch + 1) * BK * THREEC + 4);
        }

#pragma unroll
        for (int k = 0; k < BK; k++) {
            float rM[8], rN[8];
            float4 m0 = *(const float4*)&As[cb][k][tRow * 8];
            float4 m1 = *(const float4*)&As[cb][k][tRow * 8 + 4];
            float4 n0 = *(const float4*)&Bs[cb][k][wn * 64 + cc * 4];
            float4 n1 = *(const float4*)&Bs[cb][k][wn * 64 + 32 + cc * 4];
            rM[0] = m0.x; rM[1] = m0.y; rM[2] = m0.z; rM[3] = m0.w;
            rM[4] = m1.x; rM[5] = m1.y; rM[6] = m1.z; rM[7] = m1.w;
            rN[0] = n0.x; rN[1] = n0.y; rN[2] = n0.z; rN[3] = n0.w;
            rN[4] = n1.x; rN[5] = n1.y; rN[6] = n1.z; rN[7] = n1.w;
#pragma unroll
            for (int i = 0; i < 8; i++)
#pragma unroll
                for (int j = 0; j < 8; j++) acc[i][j] += rM[i] * rN[j];
        }

        if (ch + 1 < NCH) {
            As[nb][ac + 0][ar] = pa0.x; As[nb][ac + 1][ar] = pa0.y;
            As[nb][ac + 2][ar] = pa0.z; As[nb][ac + 3][ar] = pa0.w;
            As[nb][ac + 4][ar] = pa1.x; As[nb][ac + 5][ar] = pa1.y;
            As[nb][ac + 6][ar] = pa1.z; As[nb][ac + 7][ar] = pa1.w;
            *(float4*)&Bs[nb][bk][bpo]      = pb0;
            *(float4*)&Bs[nb][bk][bpo + 32] = pb1;
        }
        __syncthreads();
    }

    // ---- vectorized scatter epilogue ----
    const float scale = 0.17677669529663687f;  // 32^-0.5
    const int col0 = blockIdx.x * 128 + tCol * 8;   // multiple of 8
    const int s    = col0 >> 9;                     // q/k/v select, fixed
    const int rem  = col0 & 511;
    const int hh   = rem >> 5;                      // head, fixed (8-block within 32)
    const int dd0  = rem & 31;                      // in {0,8,16,24}
    float4 bx = *(const float4*)&bias[col0];
    float4 by = *(const float4*)&bias[col0 + 4];

#pragma unroll
    for (int i = 0; i < 8; i++) {
        int row = blockIdx.y * 128 + tRow * 8 + i;
        int b = row / NTOK;
        int n = row - b * NTOK;
        float4 v0 = make_float4(acc[i][0] + bx.x, acc[i][1] + bx.y,
                                acc[i][2] + bx.z, acc[i][3] + bx.w);
        float4 v1 = make_float4(acc[i][4] + by.x, acc[i][5] + by.y,
                                acc[i][6] + by.z, acc[i][7] + by.w);
        int idx = (((b * HEADS + hh) * NTOK) + n) * HD + dd0;
        if (s == 0) {
            v0.x *= scale; v0.y *= scale; v0.z *= scale; v0.w *= scale;
            v1.x *= scale; v1.y *= scale; v1.z *= scale; v1.w *= scale;
            *(float4*)&g_q[idx] = v0;
            *(float4*)&g_q[idx + 4] = v1;
        } else if (s == 1) {
            *(float4*)&g_k[idx] = v0;
            *(float4*)&g_k[idx + 4] = v1;
        } else {
            *(float4*)&g_v[idx] = v0;
            *(float4*)&g_v[idx + 4] = v1;
        }
    }
}

// ---------------------------------------------------------------------------
// Kernel 2: attention. Gather-free bias via g_bias; float4-q scores,
// transposed-K, warp-per-row shuffle softmax, float4 PV.
// ---------------------------------------------------------------------------
__global__ __launch_bounds__(256) void attn_kernel() {
    __shared__ __align__(16) float qs[NTOK * HD];
    __shared__ __align__(16) float kst[HD][52];
    __shared__ __align__(16) float vs[NTOK * HD];
    __shared__ __align__(16) float S[NTOK][52];

    const int bh  = blockIdx.x;
    const int h   = bh & (HEADS - 1);
    const int b   = bh >> 4;
    const int tid = threadIdx.x;
    const float* bias_h = g_bias + h * NSQ;

    const int base = bh * NTOK * HD;
    for (int i = tid; i < NTOK * HD; i += 256) {
        int n = i >> 5;
        int d = i & 31;
        qs[i] = g_q[base + i];
        kst[d][n] = g_k[base + i];
        vs[i] = g_v[base + i];
    }
    if (tid < 128) {
        int d = tid >> 2;
        int c = tid & 3;
        if (c < 3) kst[d][49 + c] = 0.f;
    }
    __syncthreads();

    // ---- scores: 25 n-tiles x 13 m-tiles, 2n x 4m, float4 q, bias from table ----
    for (int t = tid; t < 325; t += 256) {
        int n0 = (t / 13) * 2;
        int m0 = (t % 13) * 4;
        bool n1ok = (n0 + 1 < NTOK);
        int n1 = n1ok ? n0 + 1 : n0;
        float a0[4] = {0.f, 0.f, 0.f, 0.f};
        float a1[4] = {0.f, 0.f, 0.f, 0.f};
#pragma unroll
        for (int d0 = 0; d0 < HD; d0 += 4) {
            float4 qa = *(const float4*)&qs[n0 * HD + d0];
            float4 qb = *(const float4*)&qs[n1 * HD + d0];
            float4 k0 = *(const float4*)&kst[d0 + 0][m0];
            float4 k1 = *(const float4*)&kst[d0 + 1][m0];
            float4 k2 = *(const float4*)&kst[d0 + 2][m0];
            float4 k3 = *(const float4*)&kst[d0 + 3][m0];
            a0[0] += qa.x * k0.x + qa.y * k1.x + qa.z * k2.x + qa.w * k3.x;
            a0[1] += qa.x * k0.y + qa.y * k1.y + qa.z * k2.y + qa.w * k3.y;
            a0[2] += qa.x * k0.z + qa.y * k1.z + qa.z * k2.z + qa.w * k3.z;
            a0[3] += qa.x * k0.w + qa.y * k1.w + qa.z * k2.w + qa.w * k3.w;
            a1[0] += qb.x * k0.x + qb.y * k1.x + qb.z * k2.x + qb.w * k3.x;
            a1[1] += qb.x * k0.y + qb.y * k1.y + qb.z * k2.y + qb.w * k3.y;
            a1[2] += qb.x * k0.z + qb.y * k1.z + qb.z * k2.z + qb.w * k3.z;
            a1[3] += qb.x * k0.w + qb.y * k1.w + qb.z * k2.w + qb.w * k3.w;
        }
#pragma unroll
        for (int j = 0; j < 4; j++) {
            int m = m0 + j;
            if (m < NTOK) {
                S[n0][m] = a0[j] + bias_h[n0 * NTOK + m];
                if (n1ok)
                    S[n0 + 1][m] = a1[j] + bias_h[(n0 + 1) * NTOK + m];
            }
        }
    }
    __syncthreads();

    // ---- softmax: warp per row ----
    {
        const int warp = tid >> 5;
        const int lane = tid & 31;
        for (int n = warp; n < NTOK; n += 8) {
            float v0 = S[n][lane];
            bool hi = (lane + 32 < NTOK);
            float v1 = hi ? S[n][lane + 32] : -1e30f;
            float mx = fmaxf(v0, v1);
#pragma unroll
            for (int o = 16; o; o >>= 1) mx = fmaxf(mx, __shfl_xor_sync(0xffffffffu, mx, o));
            float e0 = __expf(v0 - mx);
            float e1 = hi ? __expf(v1 - mx) : 0.f;
            float sum = e0 + e1;
#pragma unroll
            for (int o = 16; o; o >>= 1) sum += __shfl_xor_sync(0xffffffffu, sum, o);
            float inv = 1.f / sum;
            S[n][lane] = e0 * inv;
            if (hi) S[n][lane + 32] = e1 * inv;
        }
    }
    __syncthreads();

    // ---- PV: 25 n-tiles x 8 d4-groups, 2n x 4d, float4 S ----
    if (tid < 200) {
        int n0 = (tid >> 3) * 2;
        int d0 = (tid & 7) << 2;
        bool n1ok = (n0 + 1 < NTOK);
        int n1 = n1ok ? n0 + 1 : n0;
        float4 acc0 = make_float4(0.f, 0.f, 0.f, 0.f);
        float4 acc1 = acc0;
#pragma unroll 4
        for (int m4 = 0; m4 < 48; m4 += 4) {
            float4 s0 = *(const float4*)&S[n0][m4];
            float4 s1 = *(const float4*)&S[n1][m4];
            float4 v0 = *(const float4*)&vs[(m4 + 0) * HD + d0];
            float4 v1 = *(const float4*)&vs[(m4 + 1) * HD + d0];
            float4 v2 = *(const float4*)&vs[(m4 + 2) * HD + d0];
            float4 v3 = *(const float4*)&vs[(m4 + 3) * HD + d0];
            acc0.x += s0.x * v0.x + s0.y * v1.x + s0.z * v2.x + s0.w * v3.x;
            acc0.y += s0.x * v0.y + s0.y * v1.y + s0.z * v2.y + s0.w * v3.y;
            acc0.z += s0.x * v0.z + s0.y * v1.z + s0.z * v2.z + s0.w * v3.z;
            acc0.w += s0.x * v0.w + s0.y * v1.w + s0.z * v2.w + s0.w * v3.w;
            acc1.x += s1.x * v0.x + s1.y * v1.x + s1.z * v2.x + s1.w * v3.x;
            acc1.y += s1.x * v0.y + s1.y * v1.y + s1.z * v2.y + s1.w * v3.y;
            acc1.z += s1.x * v0.z + s1.y * v1.z + s1.z * v2.z + s1.w * v3.z;
            acc1.w += s1.x * v0.w + s1.y * v1.w + s1.z * v2.w + s1.w * v3.w;
        }
        {
            float s0 = S[n0][48];
            float s1 = S[n1][48];
            float4 v = *(const float4*)&vs[48 * HD + d0];
            acc0.x += s0 * v.x; acc0.y += s0 * v.y;
            acc0.z += s0 * v.z; acc0.w += s0 * v.w;
            acc1.x += s1 * v.x; acc1.y += s1 * v.y;
            acc1.z += s1 * v.z; acc1.w += s1 * v.w;
        }
        float* o0 = g_att + (size_t)(b * NTOK + n0) * DIM + h * HD + d0;
        *(float4*)o0 = acc0;
        if (n1ok) *(float4*)(o0 + DIM) = acc1;
    }
}

// ---------------------------------------------------------------------------
// Kernel 3: projection GEMM, BK=16, vectorized epilogue.
// ---------------------------------------------------------------------------
__global__ __launch_bounds__(256) void proj_gemm_db(const float* __restrict__ B,
                                                    const float* __restrict__ bias,
                                                    float* __restrict__ out) {
    __shared__ __align__(16) float As[2][BK][128];
    __shared__ __align__(16) float Bs[2][BK][128];

    const int tid  = threadIdx.x;
    const int lane = tid & 31;
    const int warp = tid >> 5;
    const int tRow = (warp >> 1) * 4 + (lane >> 3);
    const int tCol = (warp & 1) * 8 + (lane & 7);
    const int wn   = warp & 1;
    const int cc   = lane & 7;

    const int ar = tid >> 1;
    const int ac = (tid & 1) << 3;
    const int bk = tid >> 4;
    const int bc = (tid & 15) << 3;
    const int bpo = ((bc >> 6) << 6) | (((bc >> 3) & 7) << 2);

    const float* Abase = g_att + (size_t)blockIdx.y * 128 * DIM + (size_t)ar * DIM + ac;
    const float* Bbase = B + (size_t)bk * DIM + blockIdx.x * 128 + bc;

    float acc[8][8];
#pragma unroll
    for (int i = 0; i < 8; i++)
#pragma unroll
        for (int j = 0; j < 8; j++) acc[i][j] = 0.f;

    {
        float4 a0 = *(const float4*)(Abase);
        float4 a1 = *(const float4*)(Abase + 4);
        As[0][ac + 0][ar] = a0.x; As[0][ac + 1][ar] = a0.y;
        As[0][ac + 2][ar] = a0.z; As[0][ac + 3][ar] = a0.w;
        As[0][ac + 4][ar] = a1.x; As[0][ac + 5][ar] = a1.y;
        As[0][ac + 6][ar] = a1.z; As[0][ac + 7][ar] = a1.w;
        *(float4*)&Bs[0][bk][bpo]      = *(const float4*)(Bbase);
        *(float4*)&Bs[0][bk][bpo + 32] = *(const float4*)(Bbase + 4);
    }
    __syncthreads();

    for (int ch = 0; ch < NCH; ch++) {
        const int cb = ch & 1;
        const int nb = cb ^ 1;

        float4 pa0, pa1, pb0, pb1;
        if (ch + 1 < NCH) {
            pa0 = *(const float4*)(Abase + (ch + 1) * BK);
            pa1 = *(const float4*)(Abase + (ch + 1) * BK + 4);
            pb0 = *(const float4*)(Bbase + (size_t)(ch + 1) * BK * DIM);
            pb1 = *(const float4*)(Bbase + (size_t)(ch + 1) * BK * DIM + 4);
        }

#pragma unroll
        for (int k = 0; k < BK; k++) {
            float rM[8], rN[8];
            float4 m0 = *(const float4*)&As[cb][k][tRow * 8];
            float4 m1 = *(const float4*)&As[cb][k][tRow * 8 + 4];
            float4 n0 = *(const float4*)&Bs[cb][k][wn * 64 + cc * 4];
            float4 n1 = *(const float4*)&Bs[cb][k][wn * 64 + 32 + cc * 4];
            rM[0] = m0.x; rM[1] = m0.y; rM[2] = m0.z; rM[3] = m0.w;
            rM[4] = m1.x; rM[5] = m1.y; rM[6] = m1.z; rM[7] = m1.w;
            rN[0] = n0.x; rN[1] = n0.y; rN[2] = n0.z; rN[3] = n0.w;
            rN[4] = n1.x; rN[5] = n1.y; rN[6] = n1.z; rN[7] = n1.w;
#pragma unroll
            for (int i = 0; i < 8; i++)
#pragma unroll
                for (int j = 0; j < 8; j++) acc[i][j] += rM[i] * rN[j];
        }

        if (ch + 1 < NCH) {
            As[nb][ac + 0][ar] = pa0.x; As[nb][ac + 1][ar] = pa0.y;
            As[nb][ac + 2][ar] = pa0.z; As[nb][ac + 3][ar] = pa0.w;
            As[nb][ac + 4][ar] = pa1.x; As[nb][ac + 5][ar] = pa1.y;
            As[nb][ac + 6][ar] = pa1.z; As[nb][ac + 7][ar] = pa1.w;
            *(float4*)&Bs[nb][bk][bpo]      = pb0;
            *(float4*)&Bs[nb][bk][bpo + 32] = pb1;
        }
        __syncthreads();
    }

    const int col0 = blockIdx.x * 128 + tCol * 8;
    float4 bx = *(const float4*)&bias[col0];
    float4 by = *(const float4*)&bias[col0 + 4];
#pragma unroll
    for (int i = 0; i < 8; i++) {
        int row = blockIdx.y * 128 + tRow * 8 + i;
        float4 v0 = make_float4(acc[i][0] + bx.x, acc[i][1] + bx.y,
                                acc[i][2] + bx.z, acc[i][3] + bx.w);
        float4 v1 = make_float4(acc[i][4] + by.x, acc[i][5] + by.y,
                                acc[i][6] + by.z, acc[i][7] + by.w);
        *(float4*)&out[(size_t)row * DIM + col0]     = v0;
        *(float4*)&out[(size_t)row * DIM + col0 + 4] = v1;
    }
}

// ---------------------------------------------------------------------------
// Inputs: x, w_qkv, b_qkv, rpb_table, w_proj, b_proj, rel_index
// ---------------------------------------------------------------------------
extern "C" void kernel_launch(void* const* d_in, const int* in_sizes, int n_in,
                              void* d_out, int out_size) {
    const float* x      = (const float*)d_in[0];
    const float* w_qkv  = (const float*)d_in[1];
    const float* b_qkv  = (const float*)d_in[2];
    const float* rpb    = (const float*)d_in[3];
    const float* w_proj = (const float*)d_in[4];
    const float* b_proj = (const float*)d_in[5];
    const int*   rel    = (const int*)d_in[6];
    float* out = (float*)d_out;

    bias_precompute<<<(HEADS * NSQ + 255) / 256, 256>>>(rpb, rel);

    dim3 grid1(THREEC / 128, M_TOT / 128);   // (12, 784)
    qkv_gemm_db<<<grid1, 256>>>(x, w_qkv, b_qkv);

    attn_kernel<<<BW * HEADS, 256>>>();

    dim3 grid3(DIM / 128, M_TOT / 128);      // (4, 784)
    proj_gemm_db<<<grid3, 256>>>(w_proj, b_proj, out);
}